// round 8
// baseline (speedup 1.0000x reference)
#include <cuda_runtime.h>
#include <cuda_bf16.h>
#include <math.h>
#include <stdint.h>

#define TOKENS 8192
#define DIM    4096
#define NEXP   256
#define TOPK   8

#define TM   64
#define BK   32                 // 2 x k16 per chunk
#define NCH  (DIM / BK)         // 128
#define NTH  512

#define ROWB   256              // 8 granules of 32B; granules 0..5 used (3 splits x 2 cq)
#define STAGE  (320 * ROWB)     // rows 0..63 = A, 64..319 = B  (81920 B)
#define SMEM_BYTES (2 * STAGE)  // 163840
#define LGS  264

// pre-split W: [c][n][6 granules x 32B]; granule j = sp*2+cq, words perm (P0,P4,P1,P5,P2,P6,P3,P7)
__device__ __align__(16) char g_ws[NCH * NEXP * 192];
// pre-split X: [t][c][6 granules x 32B]  (201 MB scratch)
__device__ __align__(16) char g_xs[(size_t)TOKENS * NCH * 192];

__device__ __forceinline__ void mma_bf16(float* d,
                                         uint32_t a0, uint32_t a1, uint32_t a2, uint32_t a3,
                                         uint32_t b0, uint32_t b1) {
    asm volatile(
        "mma.sync.aligned.m16n8k16.row.col.f32.bf16.bf16.f32 "
        "{%0,%1,%2,%3},{%4,%5,%6,%7},{%8,%9},{%0,%1,%2,%3};"
        : "+f"(d[0]), "+f"(d[1]), "+f"(d[2]), "+f"(d[3])
        : "r"(a0), "r"(a1), "r"(a2), "r"(a3), "r"(b0), "r"(b1));
}

__device__ __forceinline__ uint32_t smem_u32(const void* p) {
    uint32_t a;
    asm("{ .reg .u64 t; cvta.to.shared.u64 t, %1; cvt.u32.u64 %0, t; }" : "=r"(a) : "l"(p));
    return a;
}
#define CP_ASYNC16(dst, src) \
    asm volatile("cp.async.cg.shared.global [%0], [%1], 16;" :: "r"(dst), "l"(src))
#define CP_COMMIT() asm volatile("cp.async.commit_group;" ::: "memory")
#define CP_WAIT0()  asm volatile("cp.async.wait_group 0;" ::: "memory")

__device__ __forceinline__ void split3(float v, uint16_t* h, uint16_t* m, uint16_t* l) {
    __nv_bfloat16 bh = __float2bfloat16_rn(v);
    float r1 = v - __bfloat162float(bh);
    __nv_bfloat16 bm = __float2bfloat16_rn(r1);
    __nv_bfloat16 bl = __float2bfloat16_rn(r1 - __bfloat162float(bm));
    *h = __bfloat16_as_ushort(bh);
    *m = __bfloat16_as_ushort(bm);
    *l = __bfloat16_as_ushort(bl);
}

// split 32 consecutive-k fp32 into a 192B block: granule (sp,cq), 8 words perm {0,4,1,5,2,6,3,7}
__device__ __forceinline__ void split_block32(const float* v, uint32_t* dst) {
    uint16_t H[32], M[32], L[32];
    #pragma unroll
    for (int i = 0; i < 32; ++i) split3(v[i], &H[i], &M[i], &L[i]);
    const int perm[8] = {0, 4, 1, 5, 2, 6, 3, 7};
    #pragma unroll
    for (int sp = 0; sp < 3; ++sp) {
        const uint16_t* S = (sp == 0) ? H : (sp == 1) ? M : L;
        #pragma unroll
        for (int cq = 0; cq < 2; ++cq) {
            #pragma unroll
            for (int wpos = 0; wpos < 8; ++wpos) {
                int pj = perm[wpos];
                int k0 = cq * 16 + 2 * pj;
                dst[(sp * 2 + cq) * 8 + wpos] = ((uint32_t)S[k0 + 1] << 16) | S[k0];
            }
        }
    }
}

// XLA logistic: 0.5 + 0.5 * tanh(0.5x)
__device__ __forceinline__ float xla_sigmoid(float v) {
    float x = 0.5f * v;
    float t;
    if (fabsf(x) < 0.0004f) {
        t = x;
    } else {
        float xc = fminf(fmaxf(x, -7.90531110763549805f), 7.90531110763549805f);
        float x2 = xc * xc;
        float p = -2.76076847742355e-16f;
        p = fmaf(p, x2, 2.00018790482477e-13f);
        p = fmaf(p, x2, -8.60467152213735e-11f);
        p = fmaf(p, x2, 5.12229709037114e-08f);
        p = fmaf(p, x2, 1.48572235717979e-05f);
        p = fmaf(p, x2, 6.37261928875436e-04f);
        p = fmaf(p, x2, 4.89352455891786e-03f);
        p = xc * p;
        float q = 1.19825839466702e-06f;
        q = fmaf(q, x2, 1.18534705686654e-04f);
        q = fmaf(q, x2, 2.26843463243900e-03f);
        q = fmaf(q, x2, 4.89352518554385e-03f);
        t = p / q;
    }
    return fmaf(0.5f, t, 0.5f);
}

// ============================================================================
// prepass: W split (small, 8us — unchanged)
// ============================================================================
__global__ __launch_bounds__(256) void wsplit_kernel(const float* __restrict__ w) {
    int j = blockIdx.x * 256 + threadIdx.x;   // 32768 = n*128 + c
    int c = j & 127;
    int n = j >> 7;
    const float4* src = (const float4*)(w + (size_t)n * DIM + c * BK);
    float v[32];
    #pragma unroll
    for (int i = 0; i < 8; ++i) {
        float4 f = src[i];
        v[i*4+0] = f.x; v[i*4+1] = f.y; v[i*4+2] = f.z; v[i*4+3] = f.w;
    }
    split_block32(v, (uint32_t*)(g_ws + ((size_t)c * NEXP + n) * 192));
}

// ============================================================================
// prepass: X split — smem-staged, fully coalesced read and write
// grid 2048 x 256 thr, 8 iters x 64 tc-blocks each
// ============================================================================
#define XS_ITERS 8
#define XS_TCPI  64     // (t,c)-blocks per iteration
__global__ __launch_bounds__(256) void xsplit_kernel(const float* __restrict__ x) {
    __shared__ uint32_t sbuf[XS_TCPI * 48];   // 12 KB
    const int tid = threadIdx.x;

    for (int it = 0; it < XS_ITERS; ++it) {
        const size_t tcbase = ((size_t)it * 2048 + blockIdx.x) * XS_TCPI;

        // load + split: 2 (tc,q) units per thread
        #pragma unroll
        for (int h = 0; h < 2; ++h) {
            int u   = tid + 256 * h;
            int tcl = u >> 3;          // 0..63
            int q   = u & 7;           // float4 index within 32 values
            float4 f = *(const float4*)(x + (tcbase + tcl) * 32 + q * 4);
            uint16_t H[4], M[4], L[4];
            split3(f.x, &H[0], &M[0], &L[0]);
            split3(f.y, &H[1], &M[1], &L[1]);
            split3(f.z, &H[2], &M[2], &L[2]);
            split3(f.w, &H[3], &M[3], &L[3]);
            int cq = q >> 2;
            int j0 = (q & 3) * 2;
            int w0 = (j0 & 3) * 2 + (j0 >> 2);
            int w1 = ((j0 + 1) & 3) * 2 + ((j0 + 1) >> 2);
            uint32_t* base = sbuf + tcl * 48;
            #pragma unroll
            for (int sp = 0; sp < 3; ++sp) {
                const uint16_t* S = (sp == 0) ? H : (sp == 1) ? M : L;
                uint32_t* g = base + (sp * 2 + cq) * 8;
                g[w0] = ((uint32_t)S[1] << 16) | S[0];
                g[w1] = ((uint32_t)S[3] << 16) | S[2];
            }
        }
        __syncthreads();

        // coalesced writeout: 768 uint4 = 12 KB contiguous
        uint4* dst = (uint4*)(g_xs + tcbase * 192);
        const uint4* srcs = (const uint4*)sbuf;
        #pragma unroll
        for (int i = 0; i < 3; ++i)
            dst[tid + 256 * i] = srcs[tid + 256 * i];
        __syncthreads();
    }
}

// ============================================================================
// main kernel: pure cp.async + LDS + MMA (unchanged from R7)
// ============================================================================
__global__ __launch_bounds__(NTH, 1)
void gate_bf16x3_kernel(float* __restrict__ out, int write_idx)
{
    extern __shared__ char smem[];
    const uint32_t sb = smem_u32(smem);
    const int tid    = threadIdx.x;
    const int lane   = tid & 31;
    const int wid    = tid >> 5;
    const int warp_m = wid & 1;
    const int warp_n = wid >> 1;
    const int t0     = blockIdx.x * TM;
    const int fr     = lane >> 2;
    const int fc     = lane & 3;

    float am[2][4][4], ac[2][4][4];
    #pragma unroll
    for (int tm = 0; tm < 2; ++tm)
        #pragma unroll
        for (int tn = 0; tn < 4; ++tn)
            #pragma unroll
            for (int q = 0; q < 4; ++q) { am[tm][tn][q] = 0.f; ac[tm][tn][q] = 0.f; }

    // precomputed staging addresses
    const int uA0  = tid;
    const int rA0  = uA0 / 12;
    const int mA0  = uA0 - rA0 * 12;
    const uint32_t dstA0 = (uint32_t)(rA0 * ROWB + (((mA0 >> 1) ^ (rA0 & 3)) * 32) + (mA0 & 1) * 16);
    const char* srcA0 = g_xs + (size_t)(t0 + rA0) * (NCH * 192) + mA0 * 16;

    const int uA1  = 512 + tid;
    const int rA1  = uA1 / 12;
    const int mA1  = uA1 - rA1 * 12;
    const uint32_t dstA1 = (uint32_t)(rA1 * ROWB + (((mA1 >> 1) ^ (rA1 & 3)) * 32) + (mA1 & 1) * 16);
    const char* srcA1 = g_xs + (size_t)(t0 + rA1) * (NCH * 192) + mA1 * 16;

    uint32_t dstB[6], srcB[6];
    #pragma unroll
    for (int i = 0; i < 6; ++i) {
        int u  = tid + 512 * i;
        int n  = u / 12;
        int mi = u - n * 12;
        int r  = 64 + n;
        dstB[i] = (uint32_t)(r * ROWB + (((mi >> 1) ^ (r & 3)) * 32) + (mi & 1) * 16);
        srcB[i] = (uint32_t)(n * 192 + mi * 16);
    }

    auto issue = [&](int c, int s) {
        const uint32_t sbase = sb + (uint32_t)(s * STAGE);
        const char* wb = g_ws + (size_t)c * (NEXP * 192);
        #pragma unroll
        for (int i = 0; i < 6; ++i)
            CP_ASYNC16(sbase + dstB[i], (const void*)(wb + srcB[i]));
        CP_ASYNC16(sbase + dstA0, (const void*)(srcA0 + (size_t)c * 192));
        if (tid < 256)
            CP_ASYNC16(sbase + dstA1, (const void*)(srcA1 + (size_t)c * 192));
        CP_COMMIT();
    };

    int arow[2][2];
    #pragma unroll
    for (int tm = 0; tm < 2; ++tm) {
        arow[tm][0] = warp_m * 32 + tm * 16 + fr;
        arow[tm][1] = arow[tm][0] + 8;
    }
    int brow[4];
    #pragma unroll
    for (int tn = 0; tn < 4; ++tn) brow[tn] = 64 + warp_n * 32 + tn * 8 + fr;

    issue(0, 0);
    CP_WAIT0();
    __syncthreads();

    for (int c = 0; c < NCH; ++c) {
        const int s = c & 1;
        if (c + 1 < NCH) issue(c + 1, s ^ 1);

        const char* st = smem + s * STAGE;
        #pragma unroll
        for (int cq = 0; cq < 2; ++cq) {
            uint2 A[3][2][2];
            #pragma unroll
            for (int tm = 0; tm < 2; ++tm)
                #pragma unroll
                for (int hf = 0; hf < 2; ++hf) {
                    int r = arow[tm][hf];
                    const char* pr = st + r * ROWB;
                    const int rx = r & 3;
                    A[0][tm][hf] = *(const uint2*)(pr + (((0 * 2 + cq) ^ rx) * 32) + fc * 8);
                    A[1][tm][hf] = *(const uint2*)(pr + (((1 * 2 + cq) ^ rx) * 32) + fc * 8);
                    A[2][tm][hf] = *(const uint2*)(pr + (((2 * 2 + cq) ^ rx) * 32) + fc * 8);
                }
            #pragma unroll
            for (int tn = 0; tn < 4; ++tn) {
                int r = brow[tn];
                const char* pr = st + r * ROWB;
                const int rx = r & 3;
                uint2 bh = *(const uint2*)(pr + (((0 * 2 + cq) ^ rx) * 32) + fc * 8);
                uint2 bm = *(const uint2*)(pr + (((1 * 2 + cq) ^ rx) * 32) + fc * 8);
                uint2 bl = *(const uint2*)(pr + (((2 * 2 + cq) ^ rx) * 32) + fc * 8);
                #pragma unroll
                for (int tm = 0; tm < 2; ++tm) {
                    float* dm = am[tm][tn];
                    float* dc = ac[tm][tn];
                    uint2 ah0 = A[0][tm][0], ah1 = A[0][tm][1];
                    uint2 am0 = A[1][tm][0], am1 = A[1][tm][1];
                    uint2 al0 = A[2][tm][0], al1 = A[2][tm][1];
                    mma_bf16(dm, ah0.x, ah1.x, ah0.y, ah1.y, bh.x, bh.y);  // hh
                    mma_bf16(dc, ah0.x, ah1.x, ah0.y, ah1.y, bm.x, bm.y);  // hm
                    mma_bf16(dc, am0.x, am1.x, am0.y, am1.y, bh.x, bh.y);  // mh
                    mma_bf16(dc, am0.x, am1.x, am0.y, am1.y, bm.x, bm.y);  // mm
                    mma_bf16(dc, ah0.x, ah1.x, ah0.y, ah1.y, bl.x, bl.y);  // hl
                    mma_bf16(dc, al0.x, al1.x, al0.y, al1.y, bh.x, bh.y);  // lh
                }
            }
        }

        CP_WAIT0();
        __syncthreads();
    }

    // epilogue: logits -> smem [64][LGS]
    float* lg = (float*)smem;
    #pragma unroll
    for (int tm = 0; tm < 2; ++tm) {
        int r = warp_m * 32 + tm * 16 + fr;
        #pragma unroll
        for (int tn = 0; tn < 4; ++tn) {
            int cc = warp_n * 32 + tn * 8 + fc * 2;
            float v0 = am[tm][tn][0] + ac[tm][tn][0];
            float v1 = am[tm][tn][1] + ac[tm][tn][1];
            float v2 = am[tm][tn][2] + ac[tm][tn][2];
            float v3 = am[tm][tn][3] + ac[tm][tn][3];
            *(float2*)(lg + (size_t)r * LGS + cc)       = make_float2(v0, v1);
            *(float2*)(lg + (size_t)(r + 8) * LGS + cc) = make_float2(v2, v3);
        }
    }
    __syncthreads();

    // top-8 on sigmoid scores, lower-index tie-break
    #pragma unroll
    for (int it = 0; it < 4; ++it) {
        const int t = wid * 4 + it;
        float v[8];
        #pragma unroll
        for (int j = 0; j < 8; ++j)
            v[j] = xla_sigmoid(lg[(size_t)t * LGS + lane + j * 32]);

        float topv[8];
        int   topi[8];
        unsigned used = 0;

        #pragma unroll
        for (int r = 0; r < 8; ++r) {
            float best = -INFINITY;
            int   bidx = 0x7fffffff;
            #pragma unroll
            for (int j = 0; j < 8; ++j) {
                if (!((used >> j) & 1u)) {
                    float val = v[j];
                    int   id  = lane + j * 32;
                    if (val > best || (val == best && id < bidx)) { best = val; bidx = id; }
                }
            }
            #pragma unroll
            for (int off = 16; off > 0; off >>= 1) {
                float ov = __shfl_xor_sync(0xffffffffu, best, off);
                int   oi = __shfl_xor_sync(0xffffffffu, bidx, off);
                if (ov > best || (ov == best && oi < bidx)) { best = ov; bidx = oi; }
            }
            topv[r] = best;
            topi[r] = bidx;
            if ((bidx & 31) == lane) used |= 1u << (bidx >> 5);
        }

        float sum = 0.f;
        #pragma unroll
        for (int r = 0; r < 8; ++r) sum += topv[r];
        float inv = 1.f / sum;

        if (lane == 0) {
            int gt = t0 + t;
            #pragma unroll
            for (int r = 0; r < 8; ++r)
                out[(size_t)gt * TOPK + r] = topv[r] * inv;
            if (write_idx) {
                #pragma unroll
                for (int r = 0; r < 8; ++r)
                    out[(size_t)TOKENS * TOPK + (size_t)gt * TOPK + r] = (float)topi[r];
            }
        }
    }
}

extern "C" void kernel_launch(void* const* d_in, const int* in_sizes, int n_in,
                              void* d_out, int out_size)
{
    const float* x = (const float*)d_in[0];   // [TOKENS, DIM]
    const float* w = (const float*)d_in[1];   // [NEXP, DIM]
    float* out = (float*)d_out;

    int write_idx = (out_size >= 2 * TOKENS * TOPK) ? 1 : 0;

    cudaFuncSetAttribute(gate_bf16x3_kernel, cudaFuncAttributeMaxDynamicSharedMemorySize, SMEM_BYTES);

    wsplit_kernel<<<(NEXP * NCH) / 256, 256>>>(w);
    xsplit_kernel<<<2048, 256>>>(x);
    gate_bf16x3_kernel<<<TOKENS / TM, NTH, SMEM_BYTES>>>(out, write_idx);
}

// round 9
// speedup vs baseline: 1.7379x; 1.7379x over previous
#include <cuda_runtime.h>
#include <cuda_bf16.h>
#include <math.h>
#include <stdint.h>

#define TOKENS 8192
#define DIM    4096
#define NEXP   256
#define TOPK   8

#define TM   64
#define BK   32                 // 2 x k16 per chunk
#define NCH  (DIM / BK)         // 128
#define NTH  512

#define ROWB   256              // 8 granules of 32B; granules 0..5 used (3 splits x 2 cq)
#define STAGE  (320 * ROWB)     // rows 0..63 = A, 64..319 = B  (81920 B)
#define SMEM_BYTES (2 * STAGE)  // 163840
#define LGS  264

// pre-split W: [c][n][6 granules x 32B]; granule j = sp*2+cq, words perm (P0,P4,P1,P5,P2,P6,P3,P7)
__device__ __align__(16) char g_ws[NCH * NEXP * 192];

__device__ __forceinline__ void mma_bf16(float* d,
                                         uint32_t a0, uint32_t a1, uint32_t a2, uint32_t a3,
                                         uint32_t b0, uint32_t b1) {
    asm volatile(
        "mma.sync.aligned.m16n8k16.row.col.f32.bf16.bf16.f32 "
        "{%0,%1,%2,%3},{%4,%5,%6,%7},{%8,%9},{%0,%1,%2,%3};"
        : "+f"(d[0]), "+f"(d[1]), "+f"(d[2]), "+f"(d[3])
        : "r"(a0), "r"(a1), "r"(a2), "r"(a3), "r"(b0), "r"(b1));
}

__device__ __forceinline__ uint32_t smem_u32(const void* p) {
    uint32_t a;
    asm("{ .reg .u64 t; cvta.to.shared.u64 t, %1; cvt.u32.u64 %0, t; }" : "=r"(a) : "l"(p));
    return a;
}
#define CP_ASYNC16(dst, src) \
    asm volatile("cp.async.cg.shared.global [%0], [%1], 16;" :: "r"(dst), "l"(src))
#define CP_COMMIT() asm volatile("cp.async.commit_group;" ::: "memory")
#define CP_WAIT0()  asm volatile("cp.async.wait_group 0;" ::: "memory")

// EXACT truncation 3-way split: v = h + m + l bit-exactly (24 = 8+8+8 mantissa bits).
// Returns the three fp32 values whose low 16 bits are zero (bf16-exact).
__device__ __forceinline__ void tsplit3(float v, float* h, float* m, float* l) {
    float hh = __uint_as_float(__float_as_uint(v) & 0xFFFF0000u);
    float r  = v - hh;
    float mm = __uint_as_float(__float_as_uint(r) & 0xFFFF0000u);
    *h = hh; *m = mm; *l = r - mm;
}
// pack bf16(a), bf16(b) -> (b16<<16)|a16, where a,b are bf16-exact fp32
__device__ __forceinline__ uint32_t packhi(float a, float b) {
    return __byte_perm(__float_as_uint(a), __float_as_uint(b), 0x7632);
}

// XLA logistic: 0.5 + 0.5 * tanh(0.5x)
__device__ __forceinline__ float xla_sigmoid(float v) {
    float x = 0.5f * v;
    float t;
    if (fabsf(x) < 0.0004f) {
        t = x;
    } else {
        float xc = fminf(fmaxf(x, -7.90531110763549805f), 7.90531110763549805f);
        float x2 = xc * xc;
        float p = -2.76076847742355e-16f;
        p = fmaf(p, x2, 2.00018790482477e-13f);
        p = fmaf(p, x2, -8.60467152213735e-11f);
        p = fmaf(p, x2, 5.12229709037114e-08f);
        p = fmaf(p, x2, 1.48572235717979e-05f);
        p = fmaf(p, x2, 6.37261928875436e-04f);
        p = fmaf(p, x2, 4.89352455891786e-03f);
        p = xc * p;
        float q = 1.19825839466702e-06f;
        q = fmaf(q, x2, 1.18534705686654e-04f);
        q = fmaf(q, x2, 2.26843463243900e-03f);
        q = fmaf(q, x2, 4.89352518554385e-03f);
        t = p / q;
    }
    return fmaf(0.5f, t, 0.5f);
}

// ============================================================================
// W prepass: truncation split into [c][n][192B] permuted blocks
// ============================================================================
__global__ __launch_bounds__(256) void wsplit_kernel(const float* __restrict__ w) {
    int j = blockIdx.x * 256 + threadIdx.x;   // 32768 = n*128 + c
    int c = j & 127;
    int n = j >> 7;
    const float4* src = (const float4*)(w + (size_t)n * DIM + c * BK);
    float v[32];
    #pragma unroll
    for (int i = 0; i < 8; ++i) {
        float4 f = src[i];
        v[i*4+0] = f.x; v[i*4+1] = f.y; v[i*4+2] = f.z; v[i*4+3] = f.w;
    }
    float H[32], M[32], L[32];
    #pragma unroll
    for (int i = 0; i < 32; ++i) tsplit3(v[i], &H[i], &M[i], &L[i]);

    uint32_t* dst = (uint32_t*)(g_ws + ((size_t)c * NEXP + n) * 192);
    const int perm[8] = {0, 4, 1, 5, 2, 6, 3, 7};
    #pragma unroll
    for (int sp = 0; sp < 3; ++sp) {
        const float* S = (sp == 0) ? H : (sp == 1) ? M : L;
        #pragma unroll
        for (int cq = 0; cq < 2; ++cq) {
            #pragma unroll
            for (int wpos = 0; wpos < 8; ++wpos) {
                int pj = perm[wpos];
                int k0 = cq * 16 + 2 * pj;
                dst[(sp * 2 + cq) * 8 + wpos] = packhi(S[k0], S[k0 + 1]);
            }
        }
    }
}

// ============================================================================
// main kernel: fused — W via cp.async from g_ws, x split in-register (cheap)
// ============================================================================
__global__ __launch_bounds__(NTH, 1)
void gate_bf16x3_kernel(const float* __restrict__ x,
                        float* __restrict__ out,
                        int write_idx)
{
    extern __shared__ char smem[];
    const uint32_t sb = smem_u32(smem);
    const int tid    = threadIdx.x;
    const int lane   = tid & 31;
    const int wid    = tid >> 5;
    const int warp_m = wid & 1;      // 2 x 32 tokens
    const int warp_n = wid >> 1;     // 8 x 32 experts
    const int t0     = blockIdx.x * TM;
    const int fr     = lane >> 2;
    const int fc     = lane & 3;

    float am[2][4][4], ac[2][4][4];
    #pragma unroll
    for (int tm = 0; tm < 2; ++tm)
        #pragma unroll
        for (int tn = 0; tn < 4; ++tn)
            #pragma unroll
            for (int q = 0; q < 4; ++q) { am[tm][tn][q] = 0.f; ac[tm][tn][q] = 0.f; }

    // W staging: thread does u = tid + 512*i, i = 0..5 (3072 16B units)
    uint32_t dstB[6], srcB[6];
    #pragma unroll
    for (int i = 0; i < 6; ++i) {
        int u  = tid + 512 * i;
        int n  = u / 12;
        int mi = u - n * 12;
        int r  = 64 + n;
        dstB[i] = (uint32_t)(r * ROWB + (((mi >> 1) ^ (r & 3)) * 32) + (mi & 1) * 16);
        srcB[i] = (uint32_t)(n * 192 + mi * 16);
    }

    // x staging: thread -> row r = tid>>3, q = tid&7 (4 k-values at q*4)
    const int xr  = tid >> 3;
    const int xq  = tid & 7;
    const int xcq = xq >> 2;
    const int xj0 = (xq & 3) * 2;
    const int xp0 = (xj0 & 3) * 2 + (xj0 >> 2);
    const int xp1 = ((xj0 + 1) & 3) * 2 + ((xj0 + 1) >> 2);
    const float* xsrc = x + (size_t)(t0 + xr) * DIM + xq * 4;

    float4 ra;

    auto issue = [&](int c, int s) {
        const uint32_t sbase = sb + (uint32_t)(s * STAGE);
        const char* wb = g_ws + (size_t)c * (NEXP * 192);
        #pragma unroll
        for (int i = 0; i < 6; ++i)
            CP_ASYNC16(sbase + dstB[i], (const void*)(wb + srcB[i]));
        CP_COMMIT();
        ra = *(const float4*)(xsrc + (size_t)c * BK);
    };

    auto finish_x = [&](int s) {
        float H[4], M[4], L[4];
        tsplit3(ra.x, &H[0], &M[0], &L[0]);
        tsplit3(ra.y, &H[1], &M[1], &L[1]);
        tsplit3(ra.z, &H[2], &M[2], &L[2]);
        tsplit3(ra.w, &H[3], &M[3], &L[3]);
        uint32_t* base = (uint32_t*)(smem + s * STAGE + xr * ROWB);
        const int rx = xr & 3;
        #pragma unroll
        for (int sp = 0; sp < 3; ++sp) {
            const float* S = (sp == 0) ? H : (sp == 1) ? M : L;
            uint32_t* g = base + (((sp * 2 + xcq) ^ rx) * 8);
            g[xp0] = packhi(S[0], S[1]);
            g[xp1] = packhi(S[2], S[3]);
        }
    };

    // fragment row bases
    int arow[2][2];
    #pragma unroll
    for (int tm = 0; tm < 2; ++tm) {
        arow[tm][0] = warp_m * 32 + tm * 16 + fr;
        arow[tm][1] = arow[tm][0] + 8;
    }
    int brow[4];
    #pragma unroll
    for (int tn = 0; tn < 4; ++tn) brow[tn] = 64 + warp_n * 32 + tn * 8 + fr;

    // prologue
    issue(0, 0);
    finish_x(0);
    CP_WAIT0();
    __syncthreads();

    for (int c = 0; c < NCH; ++c) {
        const int s = c & 1;
        if (c + 1 < NCH) issue(c + 1, s ^ 1);

        const char* st = smem + s * STAGE;
        #pragma unroll
        for (int cq = 0; cq < 2; ++cq) {
            uint2 A[3][2][2];   // [sp][tm][hf]
            #pragma unroll
            for (int tm = 0; tm < 2; ++tm)
                #pragma unroll
                for (int hf = 0; hf < 2; ++hf) {
                    int r = arow[tm][hf];
                    const char* pr = st + r * ROWB;
                    const int rx = r & 3;
                    A[0][tm][hf] = *(const uint2*)(pr + (((0 * 2 + cq) ^ rx) * 32) + fc * 8);
                    A[1][tm][hf] = *(const uint2*)(pr + (((1 * 2 + cq) ^ rx) * 32) + fc * 8);
                    A[2][tm][hf] = *(const uint2*)(pr + (((2 * 2 + cq) ^ rx) * 32) + fc * 8);
                }
            #pragma unroll
            for (int tn = 0; tn < 4; ++tn) {
                int r = brow[tn];
                const char* pr = st + r * ROWB;
                const int rx = r & 3;
                uint2 bh = *(const uint2*)(pr + (((0 * 2 + cq) ^ rx) * 32) + fc * 8);
                uint2 bm = *(const uint2*)(pr + (((1 * 2 + cq) ^ rx) * 32) + fc * 8);
                uint2 bl = *(const uint2*)(pr + (((2 * 2 + cq) ^ rx) * 32) + fc * 8);
                #pragma unroll
                for (int tm = 0; tm < 2; ++tm) {
                    float* dm = am[tm][tn];
                    float* dc = ac[tm][tn];
                    uint2 ah0 = A[0][tm][0], ah1 = A[0][tm][1];
                    uint2 am0 = A[1][tm][0], am1 = A[1][tm][1];
                    uint2 al0 = A[2][tm][0], al1 = A[2][tm][1];
                    mma_bf16(dm, ah0.x, ah1.x, ah0.y, ah1.y, bh.x, bh.y);  // hh
                    mma_bf16(dc, ah0.x, ah1.x, ah0.y, ah1.y, bm.x, bm.y);  // hm
                    mma_bf16(dc, am0.x, am1.x, am0.y, am1.y, bh.x, bh.y);  // mh
                    mma_bf16(dc, am0.x, am1.x, am0.y, am1.y, bm.x, bm.y);  // mm
                    mma_bf16(dc, ah0.x, ah1.x, ah0.y, ah1.y, bl.x, bl.y);  // hl
                    mma_bf16(dc, al0.x, al1.x, al0.y, al1.y, bh.x, bh.y);  // lh
                }
            }
        }

        if (c + 1 < NCH) finish_x(s ^ 1);
        CP_WAIT0();
        __syncthreads();
    }

    // epilogue: logits -> smem [64][LGS]
    float* lg = (float*)smem;
    #pragma unroll
    for (int tm = 0; tm < 2; ++tm) {
        int r = warp_m * 32 + tm * 16 + fr;
        #pragma unroll
        for (int tn = 0; tn < 4; ++tn) {
            int cc = warp_n * 32 + tn * 8 + fc * 2;
            float v0 = am[tm][tn][0] + ac[tm][tn][0];
            float v1 = am[tm][tn][1] + ac[tm][tn][1];
            float v2 = am[tm][tn][2] + ac[tm][tn][2];
            float v3 = am[tm][tn][3] + ac[tm][tn][3];
            *(float2*)(lg + (size_t)r * LGS + cc)       = make_float2(v0, v1);
            *(float2*)(lg + (size_t)(r + 8) * LGS + cc) = make_float2(v2, v3);
        }
    }
    __syncthreads();

    // top-8 on sigmoid scores, lower-index tie-break
    #pragma unroll
    for (int it = 0; it < 4; ++it) {
        const int t = wid * 4 + it;
        float v[8];
        #pragma unroll
        for (int j = 0; j < 8; ++j)
            v[j] = xla_sigmoid(lg[(size_t)t * LGS + lane + j * 32]);

        float topv[8];
        int   topi[8];
        unsigned used = 0;

        #pragma unroll
        for (int r = 0; r < 8; ++r) {
            float best = -INFINITY;
            int   bidx = 0x7fffffff;
            #pragma unroll
            for (int j = 0; j < 8; ++j) {
                if (!((used >> j) & 1u)) {
                    float val = v[j];
                    int   id  = lane + j * 32;
                    if (val > best || (val == best && id < bidx)) { best = val; bidx = id; }
                }
            }
            #pragma unroll
            for (int off = 16; off > 0; off >>= 1) {
                float ov = __shfl_xor_sync(0xffffffffu, best, off);
                int   oi = __shfl_xor_sync(0xffffffffu, bidx, off);
                if (ov > best || (ov == best && oi < bidx)) { best = ov; bidx = oi; }
            }
            topv[r] = best;
            topi[r] = bidx;
            if ((bidx & 31) == lane) used |= 1u << (bidx >> 5);
        }

        float sum = 0.f;
        #pragma unroll
        for (int r = 0; r < 8; ++r) sum += topv[r];
        float inv = 1.f / sum;

        if (lane == 0) {
            int gt = t0 + t;
            #pragma unroll
            for (int r = 0; r < 8; ++r)
                out[(size_t)gt * TOPK + r] = topv[r] * inv;
            if (write_idx) {
                #pragma unroll
                for (int r = 0; r < 8; ++r)
                    out[(size_t)TOKENS * TOPK + (size_t)gt * TOPK + r] = (float)topi[r];
            }
        }
    }
}

extern "C" void kernel_launch(void* const* d_in, const int* in_sizes, int n_in,
                              void* d_out, int out_size)
{
    const float* x = (const float*)d_in[0];   // [TOKENS, DIM]
    const float* w = (const float*)d_in[1];   // [NEXP, DIM]
    float* out = (float*)d_out;

    int write_idx = (out_size >= 2 * TOKENS * TOPK) ? 1 : 0;

    cudaFuncSetAttribute(gate_bf16x3_kernel, cudaFuncAttributeMaxDynamicSharedMemorySize, SMEM_BYTES);

    wsplit_kernel<<<(NEXP * NCH) / 256, 256>>>(w);
    gate_bf16x3_kernel<<<TOKENS / TM, NTH, SMEM_BYTES>>>(x, out, write_idx);
}